// round 9
// baseline (speedup 1.0000x reference)
#include <cuda_runtime.h>
#include <cstdint>

#define NN 50000
#define EE 800000
#define RR 8
#define DIN 64
#define DHID 128
#define DOUT 64
#define NR (NN*RR)
#define LN_EPS 1e-5f

// ---- scratch (device globals; no runtime allocation); 16B-aligned ----
__device__ __align__(16) float g_agg1[(size_t)NN*RR*DIN];
__device__ __align__(16) float g_norm[NR];
__device__ __align__(16) int   g_cnt[NR];
__device__ __align__(16) float g_h[(size_t)NN*DHID];
__device__ __align__(16) float g_hall[(size_t)RR*NN*DOUT];
__device__ __align__(16) float g_oagg[(size_t)NN*DOUT];

__device__ __forceinline__ uint32_t f2tf32(float f) {
    uint32_t v;
    asm("cvt.rna.tf32.f32 %0, %1;" : "=r"(v) : "f"(f));
    return v;
}

__device__ __forceinline__ void mma_tf32(float* c, uint32_t a0, uint32_t a1,
                                         uint32_t a2, uint32_t a3,
                                         uint32_t b0, uint32_t b1) {
    asm volatile(
        "mma.sync.aligned.m16n8k8.row.col.f32.tf32.tf32.f32 "
        "{%0,%1,%2,%3}, {%4,%5,%6,%7}, {%8,%9}, {%0,%1,%2,%3};"
        : "+f"(c[0]), "+f"(c[1]), "+f"(c[2]), "+f"(c[3])
        : "r"(a0), "r"(a1), "r"(a2), "r"(a3), "r"(b0), "r"(b1));
}

__device__ __forceinline__ void red4(float* p, float4 v) {
    asm volatile("red.global.add.v4.f32 [%0], {%1,%2,%3,%4};"
                 :: "l"(p), "f"(v.x), "f"(v.y), "f"(v.z), "f"(v.w) : "memory");
}

// ------------------------------------------------------------------
__global__ void zero_kernel() {
    size_t i = (size_t)blockIdx.x * blockDim.x + threadIdx.x;
    size_t n_agg1 = (size_t)NN * RR * DIN / 4;
    size_t stride = (size_t)gridDim.x * blockDim.x;
    float4 z = make_float4(0.f, 0.f, 0.f, 0.f);
    for (size_t k = i; k < n_agg1; k += stride)
        reinterpret_cast<float4*>(g_agg1)[k] = z;
    for (size_t k = i; k < NR; k += stride)
        g_cnt[k] = 0;
}

__global__ void norm_kernel() {
    int i = blockIdx.x * blockDim.x + threadIdx.x;
    if (i < NR) {
        int c = g_cnt[i];
        g_norm[i] = c > 0 ? 1.0f / (float)c : 0.0f;
    }
}

// ------------------------------------------------------------------
// layer-1 scatter + degree count. One warp owns 32 edges.
__global__ void scatter1_kernel(const float* __restrict__ x,
                                const int* __restrict__ ei,
                                const int* __restrict__ et) {
    unsigned wid = (blockIdx.x * blockDim.x + threadIdx.x) >> 5;
    unsigned lane = threadIdx.x & 31;
    size_t e0 = (size_t)wid * 32;
    if (e0 >= EE) return;
    size_t my_e = e0 + lane;
    int s = ei[my_e];
    int d = ei[EE + my_e];
    int r = et[my_e];
    atomicAdd(&g_cnt[d * RR + r], 1);

    unsigned half = lane >> 4;
    unsigned hl = lane & 15;
#pragma unroll 4
    for (int j = 0; j < 32; j += 2) {
        int sl = j + half;
        int sj = __shfl_sync(0xffffffffu, s, sl);
        int dj = __shfl_sync(0xffffffffu, d, sl);
        int rj = __shfl_sync(0xffffffffu, r, sl);
        float4 v = *reinterpret_cast<const float4*>(x + (size_t)sj * DIN + hl * 4);
        red4(g_agg1 + ((size_t)dj * RR + rj) * DIN + hl * 4, v);
    }
}

// ------------------------------------------------------------------
// layer-1 transform (tf32, software-pipelined): h = LN(leaky(Ahat@[W1;root1]+bias1))
// K=576, 18 slabs of 32. Next slab's LDGs issued before current compute.
__global__ __launch_bounds__(256, 2) void transform1_tc(
    const float* __restrict__ x, const float* __restrict__ W1,
    const float* __restrict__ root1, const float* __restrict__ bias1,
    const float* __restrict__ gamma1, const float* __restrict__ beta1) {
    __shared__ uint32_t As[128][36];
    __shared__ uint32_t Bs[32][136];
    __shared__ float red_s[128][2];
    __shared__ float red_q[128][2];
    int tid = threadIdx.x;
    int m0 = blockIdx.x * 128;
    int lane = tid & 31, warp = tid >> 5;
    int warp_m = warp >> 1, warp_n = warp & 1;
    int qr = lane >> 2, qc = lane & 3;

    float acc[2][8][4];
#pragma unroll
    for (int mt = 0; mt < 2; mt++)
#pragma unroll
        for (int t = 0; t < 8; t++)
#pragma unroll
            for (int j = 0; j < 4; j++) acc[mt][t][j] = 0.f;

    int arow = tid >> 1, akoff = (tid & 1) * 16;
    int brow = tid >> 3, bcoff = (tid & 7) * 16;

    float avr[16], bvr[16];

    auto loadA = [&](int kk) {
        int n = m0 + arow;
        int kg = kk + akoff;
        if (n < NN) {
            if (kg < 512) {
                float nrm = g_norm[n * 8 + (kg >> 6)];
                const float4* src =
                    reinterpret_cast<const float4*>(g_agg1 + (size_t)n * 512 + kg);
#pragma unroll
                for (int i = 0; i < 4; i++) {
                    float4 v = src[i];
                    avr[4*i+0] = v.x * nrm; avr[4*i+1] = v.y * nrm;
                    avr[4*i+2] = v.z * nrm; avr[4*i+3] = v.w * nrm;
                }
            } else {
                const float4* src =
                    reinterpret_cast<const float4*>(x + (size_t)n * 64 + (kg - 512));
#pragma unroll
                for (int i = 0; i < 4; i++) {
                    float4 v = src[i];
                    avr[4*i+0] = v.x; avr[4*i+1] = v.y;
                    avr[4*i+2] = v.z; avr[4*i+3] = v.w;
                }
            }
        } else {
#pragma unroll
            for (int i = 0; i < 16; i++) avr[i] = 0.f;
        }
    };
    auto loadB = [&](int kk) {
        int kg = kk + brow;
        const float* Brow = (kg < 512) ? (W1 + (size_t)kg * 128)
                                       : (root1 + (size_t)(kg - 512) * 128);
        const float4* src = reinterpret_cast<const float4*>(Brow + bcoff);
#pragma unroll
        for (int i = 0; i < 4; i++) {
            float4 v = src[i];
            bvr[4*i+0] = v.x; bvr[4*i+1] = v.y; bvr[4*i+2] = v.z; bvr[4*i+3] = v.w;
        }
    };
    auto stsAB = [&]() {
#pragma unroll
        for (int i = 0; i < 16; i++) As[arow][akoff + i] = f2tf32(avr[i]);
#pragma unroll
        for (int i = 0; i < 16; i++) Bs[brow][bcoff + i] = f2tf32(bvr[i]);
    };

    loadA(0); loadB(0);
    stsAB();
    __syncthreads();

    for (int s = 0; s < 18; s++) {
        if (s < 17) { loadA((s + 1) * 32); loadB((s + 1) * 32); }
#pragma unroll
        for (int k8 = 0; k8 < 4; k8++) {
            int k0 = k8 * 8;
            uint32_t a[2][4];
#pragma unroll
            for (int mt = 0; mt < 2; mt++) {
                int ar = warp_m * 32 + mt * 16 + qr;
                a[mt][0] = As[ar][k0 + qc];
                a[mt][1] = As[ar + 8][k0 + qc];
                a[mt][2] = As[ar][k0 + qc + 4];
                a[mt][3] = As[ar + 8][k0 + qc + 4];
            }
#pragma unroll
            for (int t = 0; t < 8; t++) {
                int cn = warp_n * 64 + t * 8 + qr;
                uint32_t b0 = Bs[k0 + qc][cn];
                uint32_t b1 = Bs[k0 + qc + 4][cn];
                mma_tf32(acc[0][t], a[0][0], a[0][1], a[0][2], a[0][3], b0, b1);
                mma_tf32(acc[1][t], a[1][0], a[1][1], a[1][2], a[1][3], b0, b1);
            }
        }
        __syncthreads();
        if (s < 17) {
            stsAB();
            __syncthreads();
        }
    }

    // ---- epilogue: bias + LeakyReLU; cross-warp LN(128) via smem partials ----
#pragma unroll
    for (int mt = 0; mt < 2; mt++) {
        float s[2] = {0.f, 0.f}, q[2] = {0.f, 0.f};
#pragma unroll
        for (int t = 0; t < 8; t++) {
            int c = warp_n * 64 + t * 8 + 2 * qc;
            float b0v = bias1[c], b1v = bias1[c + 1];
            float u;
            u = acc[mt][t][0] + b0v; u = u >= 0.f ? u : 0.2f * u; acc[mt][t][0] = u; s[0] += u; q[0] += u * u;
            u = acc[mt][t][1] + b1v; u = u >= 0.f ? u : 0.2f * u; acc[mt][t][1] = u; s[0] += u; q[0] += u * u;
            u = acc[mt][t][2] + b0v; u = u >= 0.f ? u : 0.2f * u; acc[mt][t][2] = u; s[1] += u; q[1] += u * u;
            u = acc[mt][t][3] + b1v; u = u >= 0.f ? u : 0.2f * u; acc[mt][t][3] = u; s[1] += u; q[1] += u * u;
        }
#pragma unroll
        for (int off = 1; off <= 2; off <<= 1) {
            s[0] += __shfl_xor_sync(0xffffffffu, s[0], off);
            q[0] += __shfl_xor_sync(0xffffffffu, q[0], off);
            s[1] += __shfl_xor_sync(0xffffffffu, s[1], off);
            q[1] += __shfl_xor_sync(0xffffffffu, q[1], off);
        }
        if (qc == 0) {
            int lr = warp_m * 32 + mt * 16 + qr;
            red_s[lr][warp_n] = s[0]; red_q[lr][warp_n] = q[0];
            red_s[lr + 8][warp_n] = s[1]; red_q[lr + 8][warp_n] = q[1];
        }
    }
    __syncthreads();
#pragma unroll
    for (int mt = 0; mt < 2; mt++) {
#pragma unroll
        for (int h = 0; h < 2; h++) {
            int lr = warp_m * 32 + mt * 16 + qr + 8 * h;
            int gm = m0 + lr;
            float S = red_s[lr][0] + red_s[lr][1];
            float Q = red_q[lr][0] + red_q[lr][1];
            float mu = S * (1.f / 128.f);
            float rstd = rsqrtf(Q * (1.f / 128.f) - mu * mu + LN_EPS);
            if (gm < NN) {
#pragma unroll
                for (int t = 0; t < 8; t++) {
                    int c = warp_n * 64 + t * 8 + 2 * qc;
                    float g0 = gamma1[c], g1 = gamma1[c + 1];
                    float e0 = beta1[c], e1 = beta1[c + 1];
                    *reinterpret_cast<float2*>(&g_h[(size_t)gm * 128 + c]) =
                        make_float2((acc[mt][t][2*h] - mu) * rstd * g0 + e0,
                                    (acc[mt][t][2*h+1] - mu) * rstd * g1 + e1);
                }
            }
        }
    }
}

// ------------------------------------------------------------------
// layer-2 transform (tf32, pipelined): grid.y = r in [0,9). r<8: hall[r]=h@W2_r;
// r==8: g_oagg = h@root2. 256 threads, 8 warps as 4(M)x2(N), warp tile 32x32.
__global__ __launch_bounds__(256, 2) void transform2_tc(const float* __restrict__ W2,
                                                        const float* __restrict__ root2) {
    __shared__ uint32_t As[128][36];
    __shared__ uint32_t Bs[32][72];
    int tid = threadIdx.x;
    int m0 = blockIdx.x * 128;
    int r = blockIdx.y;
    const float* Wr = (r < RR) ? (W2 + (size_t)r * 128 * 64) : root2;
    int lane = tid & 31, warp = tid >> 5;
    int warp_m = warp >> 1, warp_n = warp & 1;
    int qr = lane >> 2, qc = lane & 3;

    float acc[2][4][4];
#pragma unroll
    for (int mt = 0; mt < 2; mt++)
#pragma unroll
        for (int t = 0; t < 4; t++)
#pragma unroll
            for (int j = 0; j < 4; j++) acc[mt][t][j] = 0.f;

    int arow = tid >> 1, akoff = (tid & 1) * 16;
    int brow = tid >> 3, bcoff = (tid & 7) * 8;

    float avr[16], bvr[8];

    auto loadA = [&](int kk) {
        int n = m0 + arow;
        if (n < NN) {
            const float4* src =
                reinterpret_cast<const float4*>(g_h + (size_t)n * 128 + kk + akoff);
#pragma unroll
            for (int i = 0; i < 4; i++) {
                float4 v = src[i];
                avr[4*i+0] = v.x; avr[4*i+1] = v.y; avr[4*i+2] = v.z; avr[4*i+3] = v.w;
            }
        } else {
#pragma unroll
            for (int i = 0; i < 16; i++) avr[i] = 0.f;
        }
    };
    auto loadB = [&](int kk) {
        const float4* src =
            reinterpret_cast<const float4*>(Wr + (size_t)(kk + brow) * 64 + bcoff);
#pragma unroll
        for (int i = 0; i < 2; i++) {
            float4 v = src[i];
            bvr[4*i+0] = v.x; bvr[4*i+1] = v.y; bvr[4*i+2] = v.z; bvr[4*i+3] = v.w;
        }
    };
    auto stsAB = [&]() {
#pragma unroll
        for (int i = 0; i < 16; i++) As[arow][akoff + i] = f2tf32(avr[i]);
#pragma unroll
        for (int i = 0; i < 8; i++) Bs[brow][bcoff + i] = f2tf32(bvr[i]);
    };

    loadA(0); loadB(0);
    stsAB();
    __syncthreads();

    for (int s = 0; s < 4; s++) {
        if (s < 3) { loadA((s + 1) * 32); loadB((s + 1) * 32); }
#pragma unroll
        for (int k8 = 0; k8 < 4; k8++) {
            int k0 = k8 * 8;
            uint32_t a[2][4];
#pragma unroll
            for (int mt = 0; mt < 2; mt++) {
                int ar = warp_m * 32 + mt * 16 + qr;
                a[mt][0] = As[ar][k0 + qc];
                a[mt][1] = As[ar + 8][k0 + qc];
                a[mt][2] = As[ar][k0 + qc + 4];
                a[mt][3] = As[ar + 8][k0 + qc + 4];
            }
#pragma unroll
            for (int t = 0; t < 4; t++) {
                int cn = warp_n * 32 + t * 8 + qr;
                uint32_t b0 = Bs[k0 + qc][cn];
                uint32_t b1 = Bs[k0 + qc + 4][cn];
                mma_tf32(acc[0][t], a[0][0], a[0][1], a[0][2], a[0][3], b0, b1);
                mma_tf32(acc[1][t], a[1][0], a[1][1], a[1][2], a[1][3], b0, b1);
            }
        }
        __syncthreads();
        if (s < 3) {
            stsAB();
            __syncthreads();
        }
    }

    float* dst = (r < RR) ? (g_hall + (size_t)r * NN * 64) : g_oagg;
#pragma unroll
    for (int mt = 0; mt < 2; mt++) {
        int r1 = m0 + warp_m * 32 + mt * 16 + qr;
        int r2 = r1 + 8;
#pragma unroll
        for (int t = 0; t < 4; t++) {
            int c = warp_n * 32 + t * 8 + 2 * qc;
            if (r1 < NN)
                *reinterpret_cast<float2*>(dst + (size_t)r1 * 64 + c) =
                    make_float2(acc[mt][t][0], acc[mt][t][1]);
            if (r2 < NN)
                *reinterpret_cast<float2*>(dst + (size_t)r2 * 64 + c) =
                    make_float2(acc[mt][t][2], acc[mt][t][3]);
        }
    }
}

// ------------------------------------------------------------------
// layer-2 scatter (warp-cooperative): oagg[dst,:] += norm * hall[rel,src,:]
__global__ void scatter2_kernel(const int* __restrict__ ei,
                                const int* __restrict__ et) {
    unsigned wid = (blockIdx.x * blockDim.x + threadIdx.x) >> 5;
    unsigned lane = threadIdx.x & 31;
    size_t e0 = (size_t)wid * 32;
    if (e0 >= EE) return;
    size_t my_e = e0 + lane;
    int s = ei[my_e];
    int d = ei[EE + my_e];
    int r = et[my_e];
    float nrm = g_norm[d * RR + r];

    unsigned half = lane >> 4;
    unsigned hl = lane & 15;
#pragma unroll 4
    for (int j = 0; j < 32; j += 2) {
        int sl = j + half;
        int sj = __shfl_sync(0xffffffffu, s, sl);
        int dj = __shfl_sync(0xffffffffu, d, sl);
        int rj = __shfl_sync(0xffffffffu, r, sl);
        float nj = __shfl_sync(0xffffffffu, nrm, sl);
        float4 v = *reinterpret_cast<const float4*>(
            g_hall + ((size_t)rj * NN + sj) * 64 + hl * 4);
        v.x *= nj; v.y *= nj; v.z *= nj; v.w *= nj;
        red4(g_oagg + (size_t)dj * 64 + hl * 4, v);
    }
}

// ------------------------------------------------------------------
// final: out = LN(oagg + bias2)
__global__ void final_ln(const float* __restrict__ bias2,
                         const float* __restrict__ gamma2,
                         const float* __restrict__ beta2,
                         float* __restrict__ out) {
    int t = blockIdx.x * blockDim.x + threadIdx.x;
    int n = t >> 4, hl = t & 15;
    if (n >= NN) return;
    float4 v = *reinterpret_cast<const float4*>(g_oagg + (size_t)n * 64 + hl * 4);
    float4 b = *reinterpret_cast<const float4*>(bias2 + hl * 4);
    v.x += b.x; v.y += b.y; v.z += b.z; v.w += b.w;
    float s = v.x + v.y + v.z + v.w;
    float q = v.x * v.x + v.y * v.y + v.z * v.z + v.w * v.w;
#pragma unroll
    for (int off = 8; off; off >>= 1) {
        s += __shfl_xor_sync(0xffffffffu, s, off);
        q += __shfl_xor_sync(0xffffffffu, q, off);
    }
    float mu = s * (1.f / 64.f);
    float rstd = rsqrtf(q * (1.f / 64.f) - mu * mu + LN_EPS);
    float4 g = *reinterpret_cast<const float4*>(gamma2 + hl * 4);
    float4 e = *reinterpret_cast<const float4*>(beta2 + hl * 4);
    float4 o;
    o.x = (v.x - mu) * rstd * g.x + e.x;
    o.y = (v.y - mu) * rstd * g.y + e.y;
    o.z = (v.z - mu) * rstd * g.z + e.z;
    o.w = (v.w - mu) * rstd * g.w + e.w;
    *reinterpret_cast<float4*>(out + (size_t)n * 64 + hl * 4) = o;
}

// ------------------------------------------------------------------
extern "C" void kernel_launch(void* const* d_in, const int* in_sizes, int n_in,
                              void* d_out, int out_size) {
    const float* x      = (const float*)d_in[0];
    const int*   ei     = (const int*)d_in[1];
    const int*   et     = (const int*)d_in[2];
    const float* W1     = (const float*)d_in[3];
    const float* root1  = (const float*)d_in[4];
    const float* bias1  = (const float*)d_in[5];
    const float* gamma1 = (const float*)d_in[6];
    const float* beta1  = (const float*)d_in[7];
    const float* W2     = (const float*)d_in[8];
    const float* root2  = (const float*)d_in[9];
    const float* bias2  = (const float*)d_in[10];
    const float* gamma2 = (const float*)d_in[11];
    const float* beta2  = (const float*)d_in[12];
    float*       out    = (float*)d_out;

    zero_kernel<<<1024, 256>>>();
    scatter1_kernel<<<(EE + 255) / 256, 256>>>(x, ei, et);
    norm_kernel<<<(NR + 255) / 256, 256>>>();
    int mblocks = (NN + 127) / 128;
    transform1_tc<<<mblocks, 256>>>(x, W1, root1, bias1, gamma1, beta1);
    dim3 g2(mblocks, RR + 1);
    transform2_tc<<<g2, 256>>>(W2, root2);
    scatter2_kernel<<<(EE + 255) / 256, 256>>>(ei, et);
    final_ln<<<(NN * 16 + 255) / 256, 256>>>(bias2, gamma2, beta2, out);
}